// round 14
// baseline (speedup 1.0000x reference)
#include <cuda_runtime.h>
#include <cuda_fp16.h>
#include <cstdint>

#define T_TOK 8192
#define HDIM  1024
#define NEXP  8
#define TPAD  (T_TOK + NEXP*128)

#define BM 128
#define BN 128
#define BK 64
#define NITER 16        // 1024 / 64
#define NSTAGE 3

#define NRBLK 256       // fat router blocks (indices 0..255), 32 tokens each
#define NWBLK 4096      // thin W-convert blocks (indices 256..4351)

// ---------------- device scratch ----------------
__device__ int   g_counts[NEXP];
__device__ int   g_offpad[NEXP + 1];
__device__ int   g_expert[T_TOK];
__device__ float g_gate[T_TOK];
__device__ int   g_tokpad[TPAD];
__device__ int   g_done;                                    // router-completion ticket
__device__ __half g_xh[(size_t)T_TOK * HDIM];               // token order
__device__ __half g_wh[(size_t)NEXP * HDIM * HDIM];         // [e][n][k]

// ---------------- helpers ----------------
__device__ __forceinline__ uint32_t smem_u32(const void* p) {
    uint32_t a;
    asm("{ .reg .u64 t; cvta.to.shared.u64 t, %1; cvt.u32.u64 %0, t; }" : "=r"(a) : "l"(p));
    return a;
}
__device__ __forceinline__ void cp16(uint32_t dst, const void* src) {
    asm volatile("cp.async.cg.shared.global [%0], [%1], 16;" :: "r"(dst), "l"(src));
}
__device__ __forceinline__ void cp_commit() {
    asm volatile("cp.async.commit_group;" ::: "memory");
}
template <int N>
__device__ __forceinline__ void cp_wait() {
    asm volatile("cp.async.wait_group %0;" :: "n"(N) : "memory");
}
#define LDSM4(R, addr) \
    asm volatile("ldmatrix.sync.aligned.m8n8.x4.shared.b16 {%0,%1,%2,%3}, [%4];" \
                 : "=r"((R)[0]), "=r"((R)[1]), "=r"((R)[2]), "=r"((R)[3]) : "r"(addr))
#define MMA16816(D, A, B0, B1) \
    asm volatile("mma.sync.aligned.m16n8k16.row.col.f32.f16.f16.f32 " \
                 "{%0,%1,%2,%3}, {%4,%5,%6,%7}, {%8,%9}, {%0,%1,%2,%3};" \
                 : "+f"((D)[0]), "+f"((D)[1]), "+f"((D)[2]), "+f"((D)[3]) \
                 : "r"((A)[0]), "r"((A)[1]), "r"((A)[2]), "r"((A)[3]), "r"(B0), "r"(B1))

// ============ phase 1: merged prep ============
// blocks 0..255    : fat router blocks (32 tokens; rw staged once)
// blocks 256..4351 : thin W transpose blocks (one 64k x 32n tile each)
// last router block to finish also performs the token dispatch (overlapped)
__global__ __launch_bounds__(256)
void prep_kernel(const float* __restrict__ x,
                 const float* __restrict__ rw,
                 const float* __restrict__ rb,
                 const float* __restrict__ ew) {
    __shared__ union {
        float rws[NEXP][1028];    // router weights transposed (32.9 KB)
        float tile[64][33];       // W-transpose staging (8.4 KB)
    } sm;
    __shared__ int s_cnt[NEXP];
    __shared__ int s_cur[NEXP];
    __shared__ int s_flag;

    const int tid = threadIdx.x;
    const int lane = tid & 31;

    if (blockIdx.x < NRBLK) {
        // ---- stage rw[h][e] -> rws[e][h] (once per 32 tokens) ----
#pragma unroll
        for (int i = 0; i < 32; i++) {
            int idx = tid + i * 256;            // 8192 elements
            sm.rws[idx & 7][idx >> 3] = rw[idx];
        }
        __syncthreads();

        // ---- router + fp16 convert: 8 warps x 4 sequential tokens ----
        const int wid = tid >> 5;
#pragma unroll 1
        for (int it = 0; it < 4; it++) {
            int gwarp = blockIdx.x * 32 + wid * 4 + it;
            const float* xr = x + (size_t)gwarp * HDIM;
            __half* hp = g_xh + (size_t)gwarp * HDIM;
            float acc[NEXP];
#pragma unroll
            for (int e = 0; e < NEXP; e++) acc[e] = 0.f;

#pragma unroll
            for (int i = 0; i < HDIM / 128; i++) {
                int h = (i * 32 + lane) * 4;
                float4 xv = *reinterpret_cast<const float4*>(xr + h);
                __half2 c0 = __floats2half2_rn(xv.x, xv.y);
                __half2 c1 = __floats2half2_rn(xv.z, xv.w);
                uint2 pk;
                pk.x = *reinterpret_cast<uint32_t*>(&c0);
                pk.y = *reinterpret_cast<uint32_t*>(&c1);
                *reinterpret_cast<uint2*>(hp + h) = pk;
#pragma unroll
                for (int e = 0; e < NEXP; e++) {
                    float4 wv = *reinterpret_cast<const float4*>(&sm.rws[e][h]);
                    acc[e] += xv.x * wv.x + xv.y * wv.y + xv.z * wv.z + xv.w * wv.w;
                }
            }
#pragma unroll
            for (int e = 0; e < NEXP; e++) {
#pragma unroll
                for (int off = 16; off > 0; off >>= 1)
                    acc[e] += __shfl_xor_sync(0xffffffffu, acc[e], off);
            }
            if (lane == 0) {
                float logit[NEXP];
                float best = -1e30f;
                int   bi = 0;
#pragma unroll
                for (int e = 0; e < NEXP; e++) {
                    logit[e] = acc[e] + rb[e];
                    if (logit[e] > best) { best = logit[e]; bi = e; }
                }
                float s = 0.f;
#pragma unroll
                for (int e = 0; e < NEXP; e++) s += expf(logit[e] - best);
                g_expert[gwarp] = bi;
                g_gate[gwarp]   = 1.0f / s;
            }
        }

        // ---- completion ticket; last router block runs dispatch ----
        __syncthreads();
        if (tid == 0) {
            __threadfence();
            int old = atomicAdd(&g_done, 1);
            s_flag = (old == NRBLK - 1) ? 1 : 0;
        }
        __syncthreads();
        if (!s_flag) return;

        // ---- dispatch (single block, overlapped with W blocks) ----
        __threadfence();   // acquire g_expert written by other blocks
        if (tid < NEXP) s_cnt[tid] = 0;
        __syncthreads();
        int local[NEXP];
#pragma unroll
        for (int e = 0; e < NEXP; e++) local[e] = 0;
        for (int t = tid; t < T_TOK; t += 256) local[g_expert[t]]++;
#pragma unroll
        for (int e = 0; e < NEXP; e++)
            if (local[e]) atomicAdd(&s_cnt[e], local[e]);
        __syncthreads();
        if (tid == 0) {
            int o = 0;
#pragma unroll
            for (int e = 0; e < NEXP; e++) {
                g_counts[e] = s_cnt[e];
                g_offpad[e] = o;
                s_cur[e] = o;
                o += ((s_cnt[e] + 127) >> 7) << 7;
            }
            g_offpad[NEXP] = o;
            g_done = 0;    // reset ticket for next graph replay
        }
        __syncthreads();
        for (int t = tid; t < T_TOK; t += 256) {
            int e = g_expert[t];
            unsigned peers = __match_any_sync(0xffffffffu, e);
            int leader = __ffs(peers) - 1;
            int rank = __popc(peers & ((1u << lane) - 1));
            int base = 0;
            if (lane == leader) base = atomicAdd(&s_cur[e], __popc(peers));
            base = __shfl_sync(0xffffffffu, base, leader);
            g_tokpad[base + rank] = t;
        }
    } else {
        // ---- W transpose + fp16 convert: one 64k x 32n tile ----
        int bxc = blockIdx.x - NRBLK;
        int n0 = (bxc & 31) * 32;
        int k0 = ((bxc >> 5) & 15) * 64;
        int e  = bxc >> 9;
        int tx = tid & 31, ty = tid >> 5;   // 32 x 8
        const float* W = ew + (size_t)e * HDIM * HDIM;
#pragma unroll
        for (int p = 0; p < 8; p++)
            sm.tile[ty + p * 8][tx] = W[(size_t)(k0 + ty + p * 8) * HDIM + n0 + tx];
        __syncthreads();
        int l  = tid & 31;        // k-pair: k = 2*l
        int nr = tid >> 5;        // 0..7
        uint32_t* w32 = reinterpret_cast<uint32_t*>(g_wh);
#pragma unroll
        for (int q = 0; q < 4; q++) {
            int n = nr + q * 8;
            __half2 h = __floats2half2_rn(sm.tile[2 * l][n], sm.tile[2 * l + 1][n]);
            size_t idx = ((size_t)e * HDIM + (n0 + n)) * (HDIM / 2) + (k0 / 2 + l);
            w32[idx] = *reinterpret_cast<uint32_t*>(&h);
        }
    }
}

// ============ phase 2: grouped fp16 HMMA GEMM (round-6 geometry) ============
static constexpr uint32_t OFF_B    = 49152;   // 3 x 16KB A buffers first
static constexpr uint32_t OFF_TOK  = 98304;
static constexpr uint32_t OFF_GATE = 98816;
static constexpr uint32_t SMEM_TOTAL = 99328;

__device__ __forceinline__ void issue_stage(int j, int tid, const int* sTok, int n0,
                                            size_t ebase, uint32_t sbase) {
    int kin = j * BK;
    int buf = j % NSTAGE;
    const __half* Bb = g_wh + ebase;
    uint32_t as = sbase + (uint32_t)buf * 16384;
    uint32_t bs = sbase + OFF_B + (uint32_t)buf * 16384;
#pragma unroll
    for (int i = 0; i < 4; i++) {
        int op = tid + i * 256;
        int r = op >> 3, c = op & 7;
        cp16(as + r * 128 + ((c * 16) ^ ((r & 7) << 4)),
             g_xh + (size_t)sTok[r] * HDIM + kin + c * 8);
    }
#pragma unroll
    for (int i = 0; i < 4; i++) {
        int op = tid + i * 256;
        int r = op >> 3, c = op & 7;
        cp16(bs + r * 128 + ((c * 16) ^ ((r & 7) << 4)),
             Bb + (size_t)(n0 + r) * HDIM + kin + c * 8);
    }
    cp_commit();
}

__global__ __launch_bounds__(256, 2)
void moe_gemm_kernel(const float* __restrict__ eb, float* __restrict__ out) {
    extern __shared__ __align__(1024) char smem[];
    const int m0 = blockIdx.y * BM;
    if (m0 >= g_offpad[NEXP]) return;
    int e = 0;
    while (m0 >= g_offpad[e + 1]) e++;
    const int rows_valid = min(BM, g_offpad[e] + g_counts[e] - m0);
    const int n0 = blockIdx.x * BN;
    const int tid = threadIdx.x;
    const uint32_t sbase = smem_u32(smem);
    const size_t ebase = (size_t)e * HDIM * HDIM;
    int* sTok = (int*)(smem + OFF_TOK);
    float* sGate = (float*)(smem + OFF_GATE);

    if (tid < 128) {
        int tok = g_tokpad[m0 + tid] & (T_TOK - 1);
        sTok[tid] = tok;
        sGate[tid] = g_gate[tok];
    }
    __syncthreads();

    issue_stage(0, tid, sTok, n0, ebase, sbase);
    issue_stage(1, tid, sTok, n0, ebase, sbase);
    issue_stage(2, tid, sTok, n0, ebase, sbase);

    const int lane = tid & 31, wid = tid >> 5;
    const int warp_m = (wid >> 1) * 32;
    const int warp_n = (wid & 1) * 64;
    const int idx = lane & 7, grp = lane >> 3;

    const int arow = warp_m + (grp & 1) * 8 + idx;
    const uint32_t axor = (uint32_t)((arow & 7) << 4);
    const uint32_t acsel = (uint32_t)((grp >> 1) * 16);
    const int brow = warp_n + (grp >> 1) * 8 + idx;
    const uint32_t bxor = (uint32_t)((brow & 7) << 4);
    const uint32_t bcsel = (uint32_t)((grp & 1) * 16);

    float acc[2][8][4];
#pragma unroll
    for (int i = 0; i < 2; i++)
#pragma unroll
        for (int j = 0; j < 8; j++)
#pragma unroll
            for (int q = 0; q < 4; q++) acc[i][j][q] = 0.f;

    for (int k = 0; k < NITER; k++) {
        cp_wait<2>();
        __syncthreads();
        int buf = k % NSTAGE;
        uint32_t as = sbase + (uint32_t)buf * 16384;
        uint32_t bs = sbase + OFF_B + (uint32_t)buf * 16384;
#pragma unroll
        for (int step = 0; step < 4; step++) {
            uint32_t kc = (uint32_t)(step * 32);
            uint32_t a[2][4], b[4][4];
#pragma unroll
            for (int mt = 0; mt < 2; mt++)
                LDSM4(a[mt], as + (uint32_t)(arow + mt * 16) * 128 + ((kc + acsel) ^ axor));
#pragma unroll
            for (int bt = 0; bt < 4; bt++)
                LDSM4(b[bt], bs + (uint32_t)(brow + bt * 16) * 128 + ((kc + bcsel) ^ bxor));
#pragma unroll
            for (int mt = 0; mt < 2; mt++)
#pragma unroll
                for (int bt = 0; bt < 4; bt++) {
                    MMA16816(acc[mt][2 * bt],     a[mt], b[bt][0], b[bt][1]);
                    MMA16816(acc[mt][2 * bt + 1], a[mt], b[bt][2], b[bt][3]);
                }
        }
        __syncthreads();
        if (k + NSTAGE < NITER) issue_stage(k + NSTAGE, tid, sTok, n0, ebase, sbase);
        else cp_commit();
    }

    // epilogue
    const float* ebias = eb + (size_t)e * HDIM + n0;
    const int colq = (lane & 3) * 2;
#pragma unroll
    for (int mt = 0; mt < 2; mt++) {
        int r_lo = warp_m + mt * 16 + (lane >> 2);
        int r_hi = r_lo + 8;
        bool v_lo = r_lo < rows_valid, v_hi = r_hi < rows_valid;
        int   t_lo = sTok[r_lo],  t_hi = sTok[r_hi];
        float g_lo = sGate[r_lo], g_hi = sGate[r_hi];
        float* o_lo = out + (size_t)t_lo * HDIM + n0;
        float* o_hi = out + (size_t)t_hi * HDIM + n0;
#pragma unroll
        for (int nt = 0; nt < 8; nt++) {
            int col = warp_n + nt * 8 + colq;
            float2 bv = *reinterpret_cast<const float2*>(ebias + col);
            if (v_lo) {
                float2 v;
                v.x = g_lo * (acc[mt][nt][0] + bv.x);
                v.y = g_lo * (acc[mt][nt][1] + bv.y);
                *reinterpret_cast<float2*>(o_lo + col) = v;
            }
            if (v_hi) {
                float2 v;
                v.x = g_hi * (acc[mt][nt][2] + bv.x);
                v.y = g_hi * (acc[mt][nt][3] + bv.y);
                *reinterpret_cast<float2*>(o_hi + col) = v;
            }
        }
    }
}

// ---------------- launch ----------------
extern "C" void kernel_launch(void* const* d_in, const int* in_sizes, int n_in,
                              void* d_out, int out_size) {
    const float* x  = (const float*)d_in[0];
    const float* rw = (const float*)d_in[1];
    const float* rb = (const float*)d_in[2];
    const float* ew = (const float*)d_in[3];
    const float* eb = (const float*)d_in[4];
    float* out = (float*)d_out;

    cudaFuncSetAttribute(moe_gemm_kernel,
                         cudaFuncAttributeMaxDynamicSharedMemorySize, SMEM_TOTAL);

    prep_kernel<<<NRBLK + NWBLK, 256>>>(x, rw, rb, ew);                         // 1
    moe_gemm_kernel<<<dim3(HDIM / BN, TPAD / BM), 256, SMEM_TOTAL>>>(eb, out);  // 2
}

// round 15
// speedup vs baseline: 1.0500x; 1.0500x over previous
#include <cuda_runtime.h>
#include <cuda_fp16.h>
#include <cstdint>

#define T_TOK 8192
#define HDIM  1024
#define NEXP  8

#define BM 128
#define BN 128
#define BK 64
#define NITER 16        // 1024 / 64
#define NSTAGE 3

#define NCTA   296      // 2 x 148 co-resident persistent CTAs
#define NWCTA  148      // CTAs 0..147 convert W after routing
#define NRUNIT 1024     // router units (8 tokens each)
#define NWUNIT 4096     // W-convert units (64k x 32n tiles, kq-major)
#define NTILE  4096     // potential GEMM tiles: mi-major (64) x e (8) x ni (8)

// ---------------- device scratch ----------------
__device__ int   g_cur[NEXP];            // per-expert slot cursors
__device__ int   g_rucnt;                // completed router units
__device__ int   g_wflag[NEXP * 8 * 4];  // [e][nstrip128][kq] -> target 16
__device__ int   g_ticket;               // dynamic GEMM tile ticket
__device__ int   g_fin;                  // completion ticket (replay reset)
__device__ float g_gate[T_TOK];
__device__ int   g_tok[NEXP * T_TOK];    // fixed-capacity per-expert token lists
__device__ __half g_xh[(size_t)T_TOK * HDIM];        // token order
__device__ __half g_wh[(size_t)NEXP * HDIM * HDIM];  // [e][n][k]

// ---------------- helpers ----------------
__device__ __forceinline__ uint32_t smem_u32(const void* p) {
    uint32_t a;
    asm("{ .reg .u64 t; cvta.to.shared.u64 t, %1; cvt.u32.u64 %0, t; }" : "=r"(a) : "l"(p));
    return a;
}
__device__ __forceinline__ void cp16(uint32_t dst, const void* src) {
    asm volatile("cp.async.cg.shared.global [%0], [%1], 16;" :: "r"(dst), "l"(src));
}
__device__ __forceinline__ void cp_commit() {
    asm volatile("cp.async.commit_group;" ::: "memory");
}
template <int N>
__device__ __forceinline__ void cp_wait() {
    asm volatile("cp.async.wait_group %0;" :: "n"(N) : "memory");
}
#define LDSM4(R, addr) \
    asm volatile("ldmatrix.sync.aligned.m8n8.x4.shared.b16 {%0,%1,%2,%3}, [%4];" \
                 : "=r"((R)[0]), "=r"((R)[1]), "=r"((R)[2]), "=r"((R)[3]) : "r"(addr))
#define MMA16816(D, A, B0, B1) \
    asm volatile("mma.sync.aligned.m16n8k16.row.col.f32.f16.f16.f32 " \
                 "{%0,%1,%2,%3}, {%4,%5,%6,%7}, {%8,%9}, {%0,%1,%2,%3};" \
                 : "+f"((D)[0]), "+f"((D)[1]), "+f"((D)[2]), "+f"((D)[3]) \
                 : "r"((A)[0]), "r"((A)[1]), "r"((A)[2]), "r"((A)[3]), "r"(B0), "r"(B1))

// light block-wide spin: tid0 volatile-polls, then barrier
__device__ __forceinline__ void block_spin(volatile int* p, int target, int tid, int ns) {
    if (tid == 0) {
        while (*p < target) __nanosleep(ns);
    }
    __syncthreads();
}

// SMEM layout (dynamic 99328 B): A 3x16KB @0, B 3x16KB @49152, tok @98304, gate @98816
static constexpr uint32_t OFF_B    = 49152;
static constexpr uint32_t OFF_TOK  = 98304;
static constexpr uint32_t OFF_GATE = 98816;
static constexpr uint32_t SMEM_TOTAL = 99328;

__device__ __forceinline__ void issue_stage(int j, int tid, const int* sTok, int n0,
                                            size_t ebase, uint32_t sbase) {
    int kin = j * BK;
    int buf = j % NSTAGE;
    const __half* Bb = g_wh + ebase;
    uint32_t as = sbase + (uint32_t)buf * 16384;
    uint32_t bs = sbase + OFF_B + (uint32_t)buf * 16384;
#pragma unroll
    for (int i = 0; i < 4; i++) {
        int op = tid + i * 256;
        int r = op >> 3, c = op & 7;
        cp16(as + r * 128 + ((c * 16) ^ ((r & 7) << 4)),
             g_xh + (size_t)sTok[r] * HDIM + kin + c * 8);
    }
#pragma unroll
    for (int i = 0; i < 4; i++) {
        int op = tid + i * 256;
        int r = op >> 3, c = op & 7;
        cp16(bs + r * 128 + ((c * 16) ^ ((r & 7) << 4)),
             Bb + (size_t)(n0 + r) * HDIM + kin + c * 8);
    }
    cp_commit();
}

__global__ __launch_bounds__(256, 2)
void fused_moe_kernel(const float* __restrict__ x,
                      const float* __restrict__ rw,
                      const float* __restrict__ rb,
                      const float* __restrict__ ew,
                      const float* __restrict__ eb,
                      float* __restrict__ out) {
    extern __shared__ __align__(1024) char smem[];
    __shared__ int s_cnt[NEXP];
    __shared__ int s_tile;

    const int tid = threadIdx.x;
    const int lane = tid & 31;
    const int wid = tid >> 5;
    const uint32_t sbase = smem_u32(smem);

    // ========== phase 1 (all CTAs): router + x fp16 convert ==========
    {
        float (*rws)[1028] = reinterpret_cast<float(*)[1028]>(smem);
        // stage rw once per CTA
#pragma unroll
        for (int i = 0; i < 32; i++) {
            int idx = tid + i * 256;
            rws[idx & 7][idx >> 3] = rw[idx];
        }
        __syncthreads();

        for (int u = blockIdx.x; u < NRUNIT; u += NCTA) {
            int t = u * 8 + wid;
            const float* xr = x + (size_t)t * HDIM;
            __half* hp = g_xh + (size_t)t * HDIM;
            float acc[NEXP];
#pragma unroll
            for (int e = 0; e < NEXP; e++) acc[e] = 0.f;
#pragma unroll
            for (int i = 0; i < HDIM / 128; i++) {
                int h = (i * 32 + lane) * 4;
                float4 xv = *reinterpret_cast<const float4*>(xr + h);
                __half2 c0 = __floats2half2_rn(xv.x, xv.y);
                __half2 c1 = __floats2half2_rn(xv.z, xv.w);
                uint2 pk;
                pk.x = *reinterpret_cast<uint32_t*>(&c0);
                pk.y = *reinterpret_cast<uint32_t*>(&c1);
                *reinterpret_cast<uint2*>(hp + h) = pk;
#pragma unroll
                for (int e = 0; e < NEXP; e++) {
                    float4 wv = *reinterpret_cast<const float4*>(&rws[e][h]);
                    acc[e] += xv.x * wv.x + xv.y * wv.y + xv.z * wv.z + xv.w * wv.w;
                }
            }
#pragma unroll
            for (int e = 0; e < NEXP; e++) {
#pragma unroll
                for (int off = 16; off > 0; off >>= 1)
                    acc[e] += __shfl_xor_sync(0xffffffffu, acc[e], off);
            }
            __threadfence();   // make this lane's x-row stores visible
            __syncwarp();
            if (lane == 0) {
                float logit[NEXP];
                float best = -1e30f;
                int   bi = 0;
#pragma unroll
                for (int e = 0; e < NEXP; e++) {
                    logit[e] = acc[e] + rb[e];
                    if (logit[e] > best) { best = logit[e]; bi = e; }
                }
                float s = 0.f;
#pragma unroll
                for (int e = 0; e < NEXP; e++) s += expf(logit[e] - best);
                g_gate[t] = 1.0f / s;
                int slot = atomicAdd(&g_cur[bi], 1);
                g_tok[bi * T_TOK + slot] = t;
                __threadfence();
            }
            __syncthreads();
            if (tid == 0) atomicAdd(&g_rucnt, 1);
        }
    }
    __syncthreads();

    // ========== phase 2 (CTAs 0..147): W transpose + fp16 convert ==========
    if (blockIdx.x < NWCTA) {
        float (*tile)[33] = reinterpret_cast<float(*)[33]>(smem);
        for (int u = blockIdx.x; u < NWUNIT; u += NWCTA) {
            // kq-major ordering: quadrant 0 of every (e,n) finishes first
            int kt  = u >> 8;            // 0..15
            int rem = u & 255;
            int e   = rem >> 5;
            int n32 = rem & 31;
            int n0  = n32 * 32;
            int k0  = kt * 64;
            int tx = tid & 31, ty = tid >> 5;
            const float* W = ew + (size_t)e * HDIM * HDIM;
#pragma unroll
            for (int p = 0; p < 8; p++)
                tile[ty + p * 8][tx] = W[(size_t)(k0 + ty + p * 8) * HDIM + n0 + tx];
            __syncthreads();
            int l  = tid & 31;
            int nr = tid >> 5;
            uint32_t* w32 = reinterpret_cast<uint32_t*>(g_wh);
#pragma unroll
            for (int q = 0; q < 4; q++) {
                int n = nr + q * 8;
                __half2 h = __floats2half2_rn(tile[2 * l][n], tile[2 * l + 1][n]);
                size_t idx = ((size_t)e * HDIM + (n0 + n)) * (HDIM / 2) + (k0 / 2 + l);
                w32[idx] = *reinterpret_cast<uint32_t*>(&h);
            }
            __threadfence();
            __syncthreads();
            if (tid == 0)
                atomicAdd(&g_wflag[e * 32 + (n32 >> 2) * 4 + (kt >> 2)], 1);
            __syncthreads();
        }
    }

    // ========== phase 3 (all CTAs, dynamic): grouped GEMM ==========
    block_spin(&g_rucnt, NRUNIT, tid, 512);   // router fully committed
    __threadfence();
    if (tid < NEXP) s_cnt[tid] = atomicAdd(&g_cur[tid], 0);
    __syncthreads();
    int cnts[NEXP];
#pragma unroll
    for (int e = 0; e < NEXP; e++) cnts[e] = s_cnt[e];

    int* sTok = (int*)(smem + OFF_TOK);
    float* sGate = (float*)(smem + OFF_GATE);
    const int warp_m = (wid >> 1) * 32;
    const int warp_n = (wid & 1) * 64;
    const int idx = lane & 7, grp = lane >> 3;
    const int arow = warp_m + (grp & 1) * 8 + idx;
    const uint32_t axor = (uint32_t)((arow & 7) << 4);
    const uint32_t acsel = (uint32_t)((grp >> 1) * 16);
    const int brow = warp_n + (grp >> 1) * 8 + idx;
    const uint32_t bxor = (uint32_t)((brow & 7) << 4);
    const uint32_t bcsel = (uint32_t)((grp & 1) * 16);

    while (true) {
        if (tid == 0) s_tile = atomicAdd(&g_ticket, 1);
        __syncthreads();
        int t = s_tile;
        if (t >= NTILE) break;
        // mi-major decode: early tickets are low-mi tiles across all experts
        const int ni = t & 7;
        const int e  = (t >> 3) & 7;
        const int mi = t >> 6;
        int rows_valid = cnts[e] - mi * 128;
        if (rows_valid <= 0) continue;       // uniform across block
        rows_valid = min(rows_valid, BM);
        const int n0 = ni * BN;
        const size_t ebase = (size_t)e * HDIM * HDIM;

        if (tid < 128) {
            int tok = (tid < rows_valid) ? __ldcg(&g_tok[e * T_TOK + mi * 128 + tid]) : 0;
            sTok[tid] = tok;
            sGate[tid] = __ldcg(&g_gate[tok]);
        }
        __syncthreads();

        // quadrant-0 B data must be ready before the prologue
        volatile int* wf = (volatile int*)&g_wflag[e * 32 + ni * 4];
        block_spin(wf + 0, 16, tid, 128);

        issue_stage(0, tid, sTok, n0, ebase, sbase);
        issue_stage(1, tid, sTok, n0, ebase, sbase);
        issue_stage(2, tid, sTok, n0, ebase, sbase);

        float acc[2][8][4];
#pragma unroll
        for (int i = 0; i < 2; i++)
#pragma unroll
            for (int j = 0; j < 8; j++)
#pragma unroll
                for (int q = 0; q < 4; q++) acc[i][j][q] = 0.f;

        for (int k = 0; k < NITER; k++) {
            cp_wait<2>();
            __syncthreads();
            int buf = k % NSTAGE;
            uint32_t as = sbase + (uint32_t)buf * 16384;
            uint32_t bs = sbase + OFF_B + (uint32_t)buf * 16384;
#pragma unroll
            for (int step = 0; step < 4; step++) {
                uint32_t kc = (uint32_t)(step * 32);
                uint32_t a[2][4], b[4][4];
#pragma unroll
                for (int mt = 0; mt < 2; mt++)
                    LDSM4(a[mt], as + (uint32_t)(arow + mt * 16) * 128 + ((kc + acsel) ^ axor));
#pragma unroll
                for (int bt = 0; bt < 4; bt++)
                    LDSM4(b[bt], bs + (uint32_t)(brow + bt * 16) * 128 + ((kc + bcsel) ^ bxor));
#pragma unroll
                for (int mt = 0; mt < 2; mt++)
#pragma unroll
                    for (int bt = 0; bt < 4; bt++) {
                        MMA16816(acc[mt][2 * bt],     a[mt], b[bt][0], b[bt][1]);
                        MMA16816(acc[mt][2 * bt + 1], a[mt], b[bt][2], b[bt][3]);
                    }
            }
            __syncthreads();
            int j = k + NSTAGE;
            if (j < NITER) {
                if ((j & 3) == 0) block_spin(wf + (j >> 2), 16, tid, 128);
                issue_stage(j, tid, sTok, n0, ebase, sbase);
            } else {
                cp_commit();
            }
        }

        // epilogue
        const float* ebias = eb + (size_t)e * HDIM + n0;
        const int colq = (lane & 3) * 2;
#pragma unroll
        for (int mt = 0; mt < 2; mt++) {
            int r_lo = warp_m + mt * 16 + (lane >> 2);
            int r_hi = r_lo + 8;
            bool v_lo = r_lo < rows_valid, v_hi = r_hi < rows_valid;
            int   t_lo = sTok[r_lo],  t_hi = sTok[r_hi];
            float g_lo = sGate[r_lo], g_hi = sGate[r_hi];
            float* o_lo = out + (size_t)t_lo * HDIM + n0;
            float* o_hi = out + (size_t)t_hi * HDIM + n0;
#pragma unroll
            for (int nt = 0; nt < 8; nt++) {
                int col = warp_n + nt * 8 + colq;
                float2 bv = *reinterpret_cast<const float2*>(ebias + col);
                if (v_lo) {
                    float2 v;
                    v.x = g_lo * (acc[mt][nt][0] + bv.x);
                    v.y = g_lo * (acc[mt][nt][1] + bv.y);
                    *reinterpret_cast<float2*>(o_lo + col) = v;
                }
                if (v_hi) {
                    float2 v;
                    v.x = g_hi * (acc[mt][nt][2] + bv.x);
                    v.y = g_hi * (acc[mt][nt][3] + bv.y);
                    *reinterpret_cast<float2*>(o_hi + col) = v;
                }
            }
        }
        __syncthreads();   // protect sTok/sGate before next tile
    }
    cp_wait<0>();

    // ========== replay-state reset (last CTA) ==========
    __syncthreads();
    if (tid == 0) {
        __threadfence();
        if (atomicAdd(&g_fin, 1) == NCTA - 1) {
            g_rucnt = 0;
            g_ticket = 0;
            g_fin = 0;
#pragma unroll
            for (int e = 0; e < NEXP; e++) g_cur[e] = 0;
            for (int i = 0; i < NEXP * 8 * 4; i++) g_wflag[i] = 0;
            __threadfence();
        }
    }
}

// ---------------- launch ----------------
extern "C" void kernel_launch(void* const* d_in, const int* in_sizes, int n_in,
                              void* d_out, int out_size) {
    const float* x  = (const float*)d_in[0];
    const float* rw = (const float*)d_in[1];
    const float* rb = (const float*)d_in[2];
    const float* ew = (const float*)d_in[3];
    const float* eb = (const float*)d_in[4];
    float* out = (float*)d_out;

    cudaFuncSetAttribute(fused_moe_kernel,
                         cudaFuncAttributeMaxDynamicSharedMemorySize, SMEM_TOTAL);

    fused_moe_kernel<<<NCTA, 256, SMEM_TOTAL>>>(x, rw, rb, ew, eb, out);
}

// round 16
// speedup vs baseline: 1.3517x; 1.2874x over previous
#include <cuda_runtime.h>
#include <cuda_fp16.h>
#include <cstdint>

#define T_TOK 8192
#define HDIM  1024
#define NEXP  8
#define TPAD  (T_TOK + NEXP*128)

#define BM 128
#define BN 128
#define BK 64
#define NITER 16        // 1024 / 64
#define NSTAGE 3

#define NRBLK 1024      // router blocks (indices 0..1023)
#define NWBLK 4096      // thin W-convert blocks (indices 1024..5119)

// ---------------- device scratch ----------------
__device__ int   g_counts[NEXP];
__device__ int   g_offpad[NEXP + 1];
__device__ int   g_expert[T_TOK];
__device__ float g_gate[T_TOK];
__device__ int   g_tokpad[TPAD];
__device__ int   g_done;                                    // router-completion ticket
__device__ __half g_xh[(size_t)T_TOK * HDIM];               // token order
__device__ __half g_wh[(size_t)NEXP * HDIM * HDIM];         // [e][n][k]

// ---------------- helpers ----------------
__device__ __forceinline__ uint32_t smem_u32(const void* p) {
    uint32_t a;
    asm("{ .reg .u64 t; cvta.to.shared.u64 t, %1; cvt.u32.u64 %0, t; }" : "=r"(a) : "l"(p));
    return a;
}
__device__ __forceinline__ void cp16(uint32_t dst, const void* src) {
    asm volatile("cp.async.cg.shared.global [%0], [%1], 16;" :: "r"(dst), "l"(src));
}
__device__ __forceinline__ void cp_commit() {
    asm volatile("cp.async.commit_group;" ::: "memory");
}
template <int N>
__device__ __forceinline__ void cp_wait() {
    asm volatile("cp.async.wait_group %0;" :: "n"(N) : "memory");
}
#define LDSM4(R, addr) \
    asm volatile("ldmatrix.sync.aligned.m8n8.x4.shared.b16 {%0,%1,%2,%3}, [%4];" \
                 : "=r"((R)[0]), "=r"((R)[1]), "=r"((R)[2]), "=r"((R)[3]) : "r"(addr))
#define MMA16816(D, A, B0, B1) \
    asm volatile("mma.sync.aligned.m16n8k16.row.col.f32.f16.f16.f32 " \
                 "{%0,%1,%2,%3}, {%4,%5,%6,%7}, {%8,%9}, {%0,%1,%2,%3};" \
                 : "+f"((D)[0]), "+f"((D)[1]), "+f"((D)[2]), "+f"((D)[3]) \
                 : "r"((A)[0]), "r"((A)[1]), "r"((A)[2]), "r"((A)[3]), "r"(B0), "r"(B1))

// ============ phase 1: merged prep (R10 structure, union smem) ============
// blocks 0..1023    : router + x fp16 convert (rw staged in SMEM)
// blocks 1024..5119 : thin W transpose blocks (one 64k x 32n tile each)
// last router block to finish also performs the token dispatch (overlapped)
__global__ __launch_bounds__(256)
void prep_kernel(const float* __restrict__ x,
                 const float* __restrict__ rw,
                 const float* __restrict__ rb,
                 const float* __restrict__ ew) {
    __shared__ union {
        float rws[NEXP][1028];    // router weights transposed (32.9 KB)
        float tile[64][33];       // W-transpose staging (8.4 KB)
    } sm;
    __shared__ int s_cnt[NEXP];
    __shared__ int s_cur[NEXP];
    __shared__ int s_flag;

    const int tid = threadIdx.x;
    const int lane = tid & 31;

    if (blockIdx.x < NRBLK) {
        // ---- stage rw[h][e] -> rws[e][h] ----
#pragma unroll
        for (int i = 0; i < 32; i++) {
            int idx = tid + i * 256;            // 8192 elements
            sm.rws[idx & 7][idx >> 3] = rw[idx];
        }
        __syncthreads();

        // ---- router + fp16 convert: 8 warps, 1 token each ----
        int gwarp = blockIdx.x * 8 + (tid >> 5);
        const float* xr = x + (size_t)gwarp * HDIM;
        __half* hp = g_xh + (size_t)gwarp * HDIM;
        float acc[NEXP];
#pragma unroll
        for (int e = 0; e < NEXP; e++) acc[e] = 0.f;

#pragma unroll
        for (int i = 0; i < HDIM / 128; i++) {
            int h = (i * 32 + lane) * 4;
            float4 xv = *reinterpret_cast<const float4*>(xr + h);
            __half2 c0 = __floats2half2_rn(xv.x, xv.y);
            __half2 c1 = __floats2half2_rn(xv.z, xv.w);
            uint2 pk;
            pk.x = *reinterpret_cast<uint32_t*>(&c0);
            pk.y = *reinterpret_cast<uint32_t*>(&c1);
            *reinterpret_cast<uint2*>(hp + h) = pk;
#pragma unroll
            for (int e = 0; e < NEXP; e++) {
                float4 wv = *reinterpret_cast<const float4*>(&sm.rws[e][h]);
                acc[e] += xv.x * wv.x + xv.y * wv.y + xv.z * wv.z + xv.w * wv.w;
            }
        }
#pragma unroll
        for (int e = 0; e < NEXP; e++) {
#pragma unroll
            for (int off = 16; off > 0; off >>= 1)
                acc[e] += __shfl_xor_sync(0xffffffffu, acc[e], off);
        }
        if (lane == 0) {
            float logit[NEXP];
            float best = -1e30f;
            int   bi = 0;
#pragma unroll
            for (int e = 0; e < NEXP; e++) {
                logit[e] = acc[e] + rb[e];
                if (logit[e] > best) { best = logit[e]; bi = e; }
            }
            float s = 0.f;
#pragma unroll
            for (int e = 0; e < NEXP; e++) s += expf(logit[e] - best);
            g_expert[gwarp] = bi;
            g_gate[gwarp]   = 1.0f / s;
        }

        // ---- completion ticket; last router block runs dispatch ----
        __syncthreads();
        if (tid == 0) {
            __threadfence();
            int old = atomicAdd(&g_done, 1);
            s_flag = (old == NRBLK - 1) ? 1 : 0;
        }
        __syncthreads();
        if (!s_flag) return;

        // ---- dispatch (single block, overlapped with W blocks) ----
        __threadfence();   // acquire g_expert written by other blocks
        if (tid < NEXP) s_cnt[tid] = 0;
        __syncthreads();
        int local[NEXP];
#pragma unroll
        for (int e = 0; e < NEXP; e++) local[e] = 0;
        for (int t = tid; t < T_TOK; t += 256) local[g_expert[t]]++;
#pragma unroll
        for (int e = 0; e < NEXP; e++)
            if (local[e]) atomicAdd(&s_cnt[e], local[e]);
        __syncthreads();
        if (tid == 0) {
            int o = 0;
#pragma unroll
            for (int e = 0; e < NEXP; e++) {
                g_counts[e] = s_cnt[e];
                g_offpad[e] = o;
                s_cur[e] = o;
                o += ((s_cnt[e] + 127) >> 7) << 7;
            }
            g_offpad[NEXP] = o;
            g_done = 0;    // reset ticket for next graph replay
        }
        __syncthreads();
        for (int t = tid; t < T_TOK; t += 256) {
            int e = g_expert[t];
            unsigned peers = __match_any_sync(0xffffffffu, e);
            int leader = __ffs(peers) - 1;
            int rank = __popc(peers & ((1u << lane) - 1));
            int base = 0;
            if (lane == leader) base = atomicAdd(&s_cur[e], __popc(peers));
            base = __shfl_sync(0xffffffffu, base, leader);
            g_tokpad[base + rank] = t;
        }
    } else {
        // ---- W transpose + fp16 convert: one 64k x 32n tile ----
        int bxc = blockIdx.x - NRBLK;
        int n0 = (bxc & 31) * 32;
        int k0 = ((bxc >> 5) & 15) * 64;
        int e  = bxc >> 9;
        int tx = tid & 31, ty = tid >> 5;   // 32 x 8
        const float* W = ew + (size_t)e * HDIM * HDIM;
#pragma unroll
        for (int p = 0; p < 8; p++)
            sm.tile[ty + p * 8][tx] = W[(size_t)(k0 + ty + p * 8) * HDIM + n0 + tx];
        __syncthreads();
        int l  = tid & 31;        // k-pair: k = 2*l
        int nr = tid >> 5;        // 0..7
        uint32_t* w32 = reinterpret_cast<uint32_t*>(g_wh);
#pragma unroll
        for (int q = 0; q < 4; q++) {
            int n = nr + q * 8;
            __half2 h = __floats2half2_rn(sm.tile[2 * l][n], sm.tile[2 * l + 1][n]);
            size_t idx = ((size_t)e * HDIM + (n0 + n)) * (HDIM / 2) + (k0 / 2 + l);
            w32[idx] = *reinterpret_cast<uint32_t*>(&h);
        }
    }
}

// ============ phase 2: grouped fp16 HMMA GEMM (round-6 geometry) ============
static constexpr uint32_t OFF_B    = 49152;   // 3 x 16KB A buffers first
static constexpr uint32_t OFF_TOK  = 98304;
static constexpr uint32_t OFF_GATE = 98816;
static constexpr uint32_t SMEM_TOTAL = 99328;

__device__ __forceinline__ void issue_stage(int j, int tid, const int* sTok, int n0,
                                            size_t ebase, uint32_t sbase) {
    int kin = j * BK;
    int buf = j % NSTAGE;
    const __half* Bb = g_wh + ebase;
    uint32_t as = sbase + (uint32_t)buf * 16384;
    uint32_t bs = sbase + OFF_B + (uint32_t)buf * 16384;
#pragma unroll
    for (int i = 0; i < 4; i++) {
        int op = tid + i * 256;
        int r = op >> 3, c = op & 7;
        cp16(as + r * 128 + ((c * 16) ^ ((r & 7) << 4)),
             g_xh + (size_t)sTok[r] * HDIM + kin + c * 8);
    }
#pragma unroll
    for (int i = 0; i < 4; i++) {
        int op = tid + i * 256;
        int r = op >> 3, c = op & 7;
        cp16(bs + r * 128 + ((c * 16) ^ ((r & 7) << 4)),
             Bb + (size_t)(n0 + r) * HDIM + kin + c * 8);
    }
    cp_commit();
}

__global__ __launch_bounds__(256, 2)
void moe_gemm_kernel(const float* __restrict__ eb, float* __restrict__ out) {
    extern __shared__ __align__(1024) char smem[];
    const int m0 = blockIdx.y * BM;
    if (m0 >= g_offpad[NEXP]) return;
    int e = 0;
    while (m0 >= g_offpad[e + 1]) e++;
    const int rows_valid = min(BM, g_offpad[e] + g_counts[e] - m0);
    const int n0 = blockIdx.x * BN;
    const int tid = threadIdx.x;
    const uint32_t sbase = smem_u32(smem);
    const size_t ebase = (size_t)e * HDIM * HDIM;
    int* sTok = (int*)(smem + OFF_TOK);
    float* sGate = (float*)(smem + OFF_GATE);

    if (tid < 128) {
        int tok = g_tokpad[m0 + tid] & (T_TOK - 1);
        sTok[tid] = tok;
        sGate[tid] = g_gate[tok];
    }
    __syncthreads();

    issue_stage(0, tid, sTok, n0, ebase, sbase);
    issue_stage(1, tid, sTok, n0, ebase, sbase);
    issue_stage(2, tid, sTok, n0, ebase, sbase);

    const int lane = tid & 31, wid = tid >> 5;
    const int warp_m = (wid >> 1) * 32;
    const int warp_n = (wid & 1) * 64;
    const int idx = lane & 7, grp = lane >> 3;

    const int arow = warp_m + (grp & 1) * 8 + idx;
    const uint32_t axor = (uint32_t)((arow & 7) << 4);
    const uint32_t acsel = (uint32_t)((grp >> 1) * 16);
    const int brow = warp_n + (grp >> 1) * 8 + idx;
    const uint32_t bxor = (uint32_t)((brow & 7) << 4);
    const uint32_t bcsel = (uint32_t)((grp & 1) * 16);

    float acc[2][8][4];
#pragma unroll
    for (int i = 0; i < 2; i++)
#pragma unroll
        for (int j = 0; j < 8; j++)
#pragma unroll
            for (int q = 0; q < 4; q++) acc[i][j][q] = 0.f;

    for (int k = 0; k < NITER; k++) {
        cp_wait<2>();
        __syncthreads();
        int buf = k % NSTAGE;
        uint32_t as = sbase + (uint32_t)buf * 16384;
        uint32_t bs = sbase + OFF_B + (uint32_t)buf * 16384;
#pragma unroll
        for (int step = 0; step < 4; step++) {
            uint32_t kc = (uint32_t)(step * 32);
            uint32_t a[2][4], b[4][4];
#pragma unroll
            for (int mt = 0; mt < 2; mt++)
                LDSM4(a[mt], as + (uint32_t)(arow + mt * 16) * 128 + ((kc + acsel) ^ axor));
#pragma unroll
            for (int bt = 0; bt < 4; bt++)
                LDSM4(b[bt], bs + (uint32_t)(brow + bt * 16) * 128 + ((kc + bcsel) ^ bxor));
#pragma unroll
            for (int mt = 0; mt < 2; mt++)
#pragma unroll
                for (int bt = 0; bt < 4; bt++) {
                    MMA16816(acc[mt][2 * bt],     a[mt], b[bt][0], b[bt][1]);
                    MMA16816(acc[mt][2 * bt + 1], a[mt], b[bt][2], b[bt][3]);
                }
        }
        __syncthreads();
        if (k + NSTAGE < NITER) issue_stage(k + NSTAGE, tid, sTok, n0, ebase, sbase);
        else cp_commit();
    }

    // epilogue
    const float* ebias = eb + (size_t)e * HDIM + n0;
    const int colq = (lane & 3) * 2;
#pragma unroll
    for (int mt = 0; mt < 2; mt++) {
        int r_lo = warp_m + mt * 16 + (lane >> 2);
        int r_hi = r_lo + 8;
        bool v_lo = r_lo < rows_valid, v_hi = r_hi < rows_valid;
        int   t_lo = sTok[r_lo],  t_hi = sTok[r_hi];
        float g_lo = sGate[r_lo], g_hi = sGate[r_hi];
        float* o_lo = out + (size_t)t_lo * HDIM + n0;
        float* o_hi = out + (size_t)t_hi * HDIM + n0;
#pragma unroll
        for (int nt = 0; nt < 8; nt++) {
            int col = warp_n + nt * 8 + colq;
            float2 bv = *reinterpret_cast<const float2*>(ebias + col);
            if (v_lo) {
                float2 v;
                v.x = g_lo * (acc[mt][nt][0] + bv.x);
                v.y = g_lo * (acc[mt][nt][1] + bv.y);
                *reinterpret_cast<float2*>(o_lo + col) = v;
            }
            if (v_hi) {
                float2 v;
                v.x = g_hi * (acc[mt][nt][2] + bv.x);
                v.y = g_hi * (acc[mt][nt][3] + bv.y);
                *reinterpret_cast<float2*>(o_hi + col) = v;
            }
        }
    }
}

// ---------------- launch ----------------
extern "C" void kernel_launch(void* const* d_in, const int* in_sizes, int n_in,
                              void* d_out, int out_size) {
    const float* x  = (const float*)d_in[0];
    const float* rw = (const float*)d_in[1];
    const float* rb = (const float*)d_in[2];
    const float* ew = (const float*)d_in[3];
    const float* eb = (const float*)d_in[4];
    float* out = (float*)d_out;

    cudaFuncSetAttribute(moe_gemm_kernel,
                         cudaFuncAttributeMaxDynamicSharedMemorySize, SMEM_TOTAL);

    prep_kernel<<<NRBLK + NWBLK, 256>>>(x, rw, rb, ew);                         // 1
    moe_gemm_kernel<<<dim3(HDIM / BN, TPAD / BM), 256, SMEM_TOTAL>>>(eb, out);  // 2
}